// round 5
// baseline (speedup 1.0000x reference)
#include <cuda_runtime.h>
#include <cuda_bf16.h>
#include <math.h>
#include <stdint.h>

#define B_ 2
#define N_ 2048
#define C_ 256
#define L_ 4
#define H_ 8
#define DH_ 32
#define ROWS_ (B_ * N_)          // 4096
#define QKV_N_ (3 * C_)          // 768
#define LOG2E_ 1.4426950408889634f
#define QSC_ (0.17677669529663687f * LOG2E_)   // applied inside exp2

// ===================== scratch (device globals; no allocs allowed) =====================
__device__ float          g_x   [ROWS_ * C_];       // residual stream fp32
__device__ float          g_tmp [ROWS_ * C_];       // proj/mlp out fp32 (pre-LN)
__device__ __nv_bfloat16  g_xb  [ROWS_ * C_];       // bf16 copy of residual stream
__device__ __nv_bfloat16  g_qkvb[ROWS_ * QKV_N_];   // qkv bf16
__device__ __nv_bfloat16  g_attnb[ROWS_ * C_];      // attention out bf16
__device__ __nv_bfloat16  g_hb  [ROWS_ * C_];       // mlp hidden bf16
// transposed bf16 weights: [N][K] K-major
__device__ __nv_bfloat16  g_qkvT [L_ * QKV_N_ * C_];
__device__ __nv_bfloat16  g_projT[L_ * C_ * C_];
__device__ __nv_bfloat16  g_w1T  [L_ * C_ * C_];
__device__ __nv_bfloat16  g_w2T  [L_ * C_ * C_];

// ===================== helpers =====================
__device__ __forceinline__ uint32_t f2bf2(float lo, float hi) {
    uint32_t r;
    asm("cvt.rn.bf16x2.f32 %0, %1, %2;" : "=r"(r) : "f"(hi), "f"(lo));
    return r;
}

__device__ __forceinline__ void mma_bf16(float* d, const uint32_t* a, const uint32_t* b) {
    asm volatile(
        "mma.sync.aligned.m16n8k16.row.col.f32.bf16.bf16.f32 "
        "{%0,%1,%2,%3}, {%4,%5,%6,%7}, {%8,%9}, {%0,%1,%2,%3};"
        : "+f"(d[0]), "+f"(d[1]), "+f"(d[2]), "+f"(d[3])
        : "r"(a[0]), "r"(a[1]), "r"(a[2]), "r"(a[3]), "r"(b[0]), "r"(b[1]));
}

__device__ __forceinline__ uint32_t su32(const void* p) {
    uint32_t a;
    asm("{ .reg .u64 t; cvta.to.shared.u64 t, %1; cvt.u32.u64 %0, t; }" : "=r"(a) : "l"(p));
    return a;
}

__device__ __forceinline__ void cp16(uint32_t dst, const void* src) {
    asm volatile("cp.async.ca.shared.global [%0], [%1], 16;" :: "r"(dst), "l"(src));
}
#define CP_COMMIT() asm volatile("cp.async.commit_group;" ::: "memory")
#define CP_WAIT(Ng) asm volatile("cp.async.wait_group %0;" :: "n"(Ng) : "memory")

// ===================== weight transpose + bf16 convert =====================
__global__ __launch_bounds__(256) void transpose_kernel(
    const float* __restrict__ in, __nv_bfloat16* __restrict__ out, int K, int Nn)
{
    __shared__ float t[32][33];
    int z = blockIdx.z;
    const float* inl = in + (size_t)z * K * Nn;
    __nv_bfloat16* outl = out + (size_t)z * Nn * K;
    int tx = threadIdx.x, ty = threadIdx.y;
    int x = blockIdx.x * 32 + tx;     // n
    int y = blockIdx.y * 32 + ty;     // k
#pragma unroll
    for (int j = 0; j < 4; j++)
        t[ty + 8 * j][tx] = inl[(size_t)(y + 8 * j) * Nn + x];
    __syncthreads();
    int x2 = blockIdx.y * 32 + tx;    // k
    int y2 = blockIdx.x * 32 + ty;    // n
#pragma unroll
    for (int j = 0; j < 4; j++)
        outl[(size_t)(y2 + 8 * j) * K + x2] = __float2bfloat16(t[tx][ty + 8 * j]);
}

// ===================== positional embedding add (fp32 + bf16 copies) ==============
__global__ void addpos_kernel(const float* __restrict__ x,
                              float* __restrict__ out, __nv_bfloat16* __restrict__ outb)
{
    int n = blockIdx.x;
    int c = threadIdx.x;
    int j = c & ~1;
    float div = __expf((float)j * (-9.210340371976184f / 256.0f));
    float ang = (float)n * div;
    float pe = (c & 1) ? cosf(ang) : sinf(ang);
    size_t i0 = (size_t)n * C_ + c;
    size_t i1 = (size_t)(N_ + n) * C_ + c;
    float v0 = x[i0] + pe, v1 = x[i1] + pe;
    out[i0] = v0; out[i1] = v1;
    outb[i0] = __float2bfloat16(v0);
    outb[i1] = __float2bfloat16(v1);
}

// ===================== bf16 mma GEMM: C = A(4096x256) @ BT(Nx256)^T ===============
// grid (Nn/64, 32), 256 thr = 8 warps (4 row x 2 col), warp tile 32x32.
// K=256 in 4 chunks of 64, cp.async double-buffered.
// mode: 0 = bf16 out, no bias; 1 = fp32 out + bias; 2 = bf16 out + bias + gelu
#define AS 36   // smem row stride in u32 (32 data + 4 pad)

__global__ __launch_bounds__(256) void gemm_mma_kernel(
    const __nv_bfloat16* __restrict__ A, const __nv_bfloat16* __restrict__ BT,
    const float* __restrict__ bias, void* __restrict__ Cc, int Nn, int mode)
{
    extern __shared__ __align__(16) uint32_t gsm[];
    uint32_t* sAb[2] = {gsm,                 gsm + 128 * AS};
    uint32_t* sBb[2] = {gsm + 2 * 128 * AS,  gsm + 2 * 128 * AS + 64 * AS};

    const int tid = threadIdx.x, w = tid >> 5, lane = tid & 31;
    const int g = lane >> 2, tg = lane & 3;
    const int wm = (w & 3) * 32, wn = (w >> 2) * 32;
    const int brow = blockIdx.y * 128, bcol = blockIdx.x * 64;

    float acc[2][4][4];
#pragma unroll
    for (int mt = 0; mt < 2; mt++)
#pragma unroll
        for (int nt = 0; nt < 4; nt++)
#pragma unroll
            for (int i = 0; i < 4; i++) acc[mt][nt][i] = 0.f;

    // staging indices
    const int arow = tid >> 1, ahalf = tid & 1;     // A: 128 rows, 64B per thread
    const int brw  = tid >> 2, bq    = tid & 3;     // B: 64 rows, 32B per thread
    const char* asrc = (const char*)A  + (size_t)(brow + arow) * 512 + ahalf * 64;
    const char* bsrc = (const char*)BT + (size_t)(bcol + brw ) * 512 + bq * 32;
    const uint32_t adst[2] = { su32(&sAb[0][arow * AS + ahalf * 16]),
                               su32(&sAb[1][arow * AS + ahalf * 16]) };
    const uint32_t bdst[2] = { su32(&sBb[0][brw  * AS + bq * 8]),
                               su32(&sBb[1][brw  * AS + bq * 8]) };

    // stage chunk 0
#pragma unroll
    for (int j = 0; j < 4; j++) cp16(adst[0] + j * 16, asrc + j * 16);
#pragma unroll
    for (int j = 0; j < 2; j++) cp16(bdst[0] + j * 16, bsrc + j * 16);
    CP_COMMIT();

#pragma unroll
    for (int it = 0; it < 4; it++) {
        const int buf = it & 1;
        if (it < 3) {
            const int nb = buf ^ 1;
#pragma unroll
            for (int j = 0; j < 4; j++) cp16(adst[nb] + j * 16, asrc + (it + 1) * 128 + j * 16);
#pragma unroll
            for (int j = 0; j < 2; j++) cp16(bdst[nb] + j * 16, bsrc + (it + 1) * 128 + j * 16);
            CP_COMMIT();
            CP_WAIT(1);
        } else {
            CP_WAIT(0);
        }
        __syncthreads();
#pragma unroll
        for (int ks = 0; ks < 4; ks++) {
            uint32_t afr[2][4];
#pragma unroll
            for (int mt = 0; mt < 2; mt++) {
                int r = wm + mt * 16 + g;
                afr[mt][0] = sAb[buf][(r    ) * AS + ks * 8 + tg];
                afr[mt][1] = sAb[buf][(r + 8) * AS + ks * 8 + tg];
                afr[mt][2] = sAb[buf][(r    ) * AS + ks * 8 + tg + 4];
                afr[mt][3] = sAb[buf][(r + 8) * AS + ks * 8 + tg + 4];
            }
#pragma unroll
            for (int nt = 0; nt < 4; nt++) {
                int n = wn + nt * 8 + g;
                uint32_t bfr[2];
                bfr[0] = sBb[buf][n * AS + ks * 8 + tg];
                bfr[1] = sBb[buf][n * AS + ks * 8 + tg + 4];
#pragma unroll
                for (int mt = 0; mt < 2; mt++) mma_bf16(acc[mt][nt], afr[mt], bfr);
            }
        }
        __syncthreads();
    }

    // epilogue
#pragma unroll
    for (int mt = 0; mt < 2; mt++) {
        int r0 = brow + wm + mt * 16 + g;
#pragma unroll
        for (int nt = 0; nt < 4; nt++) {
            int cc = bcol + wn + nt * 8 + 2 * tg;
            float bi0 = 0.f, bi1 = 0.f;
            if (mode >= 1) { bi0 = bias[cc]; bi1 = bias[cc + 1]; }
            float v0 = acc[mt][nt][0] + bi0;
            float v1 = acc[mt][nt][1] + bi1;
            float v2 = acc[mt][nt][2] + bi0;
            float v3 = acc[mt][nt][3] + bi1;
            if (mode == 2) {
                v0 = 0.5f * v0 * (1.0f + erff(v0 * 0.70710678118654752f));
                v1 = 0.5f * v1 * (1.0f + erff(v1 * 0.70710678118654752f));
                v2 = 0.5f * v2 * (1.0f + erff(v2 * 0.70710678118654752f));
                v3 = 0.5f * v3 * (1.0f + erff(v3 * 0.70710678118654752f));
            }
            if (mode == 1) {
                float* dst = (float*)Cc;
                *(float2*)(dst + (size_t)r0 * Nn + cc)       = make_float2(v0, v1);
                *(float2*)(dst + (size_t)(r0 + 8) * Nn + cc) = make_float2(v2, v3);
            } else {
                uint32_t* dst = (uint32_t*)Cc;
                dst[((size_t)r0 * Nn + cc) >> 1]       = f2bf2(v0, v1);
                dst[((size_t)(r0 + 8) * Nn + cc) >> 1] = f2bf2(v2, v3);
            }
        }
    }
}

// ===================== bf16 mma flash attention (P in registers) ==================
// grid (N/128, H, B), 256 thr = 8 warps; warp w owns q rows w*16..w*16+15.
// Double-buffered K and Vt; Q staged once; P stays in registers (S-frag == A-frag).
#define QS 20   // Q/K smem row stride (16 data u32 + 4 pad)
#define VS 68   // Vt smem row stride (64 data u32 + 4 pad)
#define KROWB ((size_t)128 * QKV_N_ * 2)   // bytes per 128-token step

__global__ __launch_bounds__(256, 2) void attn_mma_kernel(
    const __nv_bfloat16* __restrict__ qkvb, __nv_bfloat16* __restrict__ outb)
{
    __shared__ __align__(16) uint32_t sQ[128 * QS];
    __shared__ __align__(16) uint32_t sK[2][128 * QS];
    __shared__ __align__(16) uint32_t sVt[2][32 * VS];

    const int tid = threadIdx.x, w = tid >> 5, lane = tid & 31;
    const int g = lane >> 2, tg = lane & 3;
    const int qt = blockIdx.x, h = blockIdx.y, b = blockIdx.z;

    const int srow = tid >> 1, half = tid & 1;   // staging: 2 threads per row
    const int colp = tid >> 2;                    // key-pair column for Vt
    const bool keyeven = (tid & 2) == 0;

    // source pointers
    const char* qsrc = (const char*)qkvb +
        ((size_t)(b * N_ + qt * 128 + srow) * QKV_N_ + h * DH_) * 2 + half * 32;
    const char* ksrc = (const char*)qkvb +
        ((size_t)(b * N_ + srow) * QKV_N_ + C_ + h * DH_) * 2 + half * 32;
    const char* vsrc = (const char*)qkvb +
        ((size_t)(b * N_ + srow) * QKV_N_ + 2 * C_ + h * DH_) * 2 + half * 32;

    const uint32_t qdst = su32(&sQ[srow * QS + half * 8]);
    const uint32_t kdst[2] = { su32(&sK[0][srow * QS + half * 8]),
                               su32(&sK[1][srow * QS + half * 8]) };

    // prologue: Q + K0 via cp.async, V0 via regs
    cp16(qdst, qsrc);           cp16(qdst + 16, qsrc + 16);
    cp16(kdst[0], ksrc);        cp16(kdst[0] + 16, ksrc + 16);
    CP_COMMIT();
    {
        const uint4* vp = (const uint4*)vsrc;
        uint4 v0 = vp[0], v1 = vp[1];
        uint32_t vv[8] = {v0.x, v0.y, v0.z, v0.w, v1.x, v1.y, v1.z, v1.w};
#pragma unroll
        for (int i = 0; i < 8; i++) {
            uint32_t o = __shfl_xor_sync(0xffffffffu, vv[i], 2);
            if (keyeven) sVt[0][(half * 16 + 2 * i    ) * VS + colp] = __byte_perm(vv[i], o, 0x5410);
            else         sVt[0][(half * 16 + 2 * i + 1) * VS + colp] = __byte_perm(vv[i], o, 0x3276);
        }
    }
    CP_WAIT(0);
    __syncthreads();

    float oacc[4][4];
#pragma unroll
    for (int nt = 0; nt < 4; nt++)
#pragma unroll
        for (int i = 0; i < 4; i++) oacc[nt][i] = 0.f;
    float m0 = -1e30f, m1 = -1e30f, l0 = 0.f, l1 = 0.f;

    for (int kt = 0; kt < N_ / 128; kt++) {
        const int buf = kt & 1, nbuf = buf ^ 1;
        uint32_t vv[8];
        if (kt < 15) {
            const char* ks2 = ksrc + (size_t)(kt + 1) * KROWB;
            cp16(kdst[nbuf], ks2); cp16(kdst[nbuf] + 16, ks2 + 16);
            CP_COMMIT();
            const uint4* vp = (const uint4*)(vsrc + (size_t)(kt + 1) * KROWB);
            uint4 v0 = vp[0], v1 = vp[1];
            vv[0] = v0.x; vv[1] = v0.y; vv[2] = v0.z; vv[3] = v0.w;
            vv[4] = v1.x; vv[5] = v1.y; vv[6] = v1.z; vv[7] = v1.w;
        }

        // ---- S = Q @ K^T : warp tile 16 x 128 (raw scores, fp32 accum) ----
        float sacc[16][4];
#pragma unroll
        for (int nt = 0; nt < 16; nt++)
#pragma unroll
            for (int i = 0; i < 4; i++) sacc[nt][i] = 0.f;
#pragma unroll
        for (int ks = 0; ks < 2; ks++) {
            uint32_t afr[4];
            afr[0] = sQ[(w * 16 + g    ) * QS + ks * 8 + tg];
            afr[1] = sQ[(w * 16 + g + 8) * QS + ks * 8 + tg];
            afr[2] = sQ[(w * 16 + g    ) * QS + ks * 8 + tg + 4];
            afr[3] = sQ[(w * 16 + g + 8) * QS + ks * 8 + tg + 4];
#pragma unroll
            for (int nt = 0; nt < 16; nt++) {
                uint32_t bfr[2];
                bfr[0] = sK[buf][(nt * 8 + g) * QS + ks * 8 + tg];
                bfr[1] = sK[buf][(nt * 8 + g) * QS + ks * 8 + tg + 4];
                mma_bf16(sacc[nt], afr, bfr);
            }
        }

        // ---- online softmax (scale folded into exp2) ----
        float nm0 = m0, nm1 = m1;
#pragma unroll
        for (int nt = 0; nt < 16; nt++) {
            nm0 = fmaxf(nm0, fmaxf(sacc[nt][0], sacc[nt][1]));
            nm1 = fmaxf(nm1, fmaxf(sacc[nt][2], sacc[nt][3]));
        }
        nm0 = fmaxf(nm0, __shfl_xor_sync(0xffffffffu, nm0, 1));
        nm0 = fmaxf(nm0, __shfl_xor_sync(0xffffffffu, nm0, 2));
        nm1 = fmaxf(nm1, __shfl_xor_sync(0xffffffffu, nm1, 1));
        nm1 = fmaxf(nm1, __shfl_xor_sync(0xffffffffu, nm1, 2));
        float f0 = exp2f((m0 - nm0) * QSC_), f1 = exp2f((m1 - nm1) * QSC_);
        m0 = nm0; m1 = nm1;

        uint32_t pa[16][2];
        float ps0 = 0.f, ps1 = 0.f;
#pragma unroll
        for (int nt = 0; nt < 16; nt++) {
            float p00 = exp2f((sacc[nt][0] - m0) * QSC_);
            float p01 = exp2f((sacc[nt][1] - m0) * QSC_);
            float p10 = exp2f((sacc[nt][2] - m1) * QSC_);
            float p11 = exp2f((sacc[nt][3] - m1) * QSC_);
            ps0 += p00 + p01;
            ps1 += p10 + p11;
            pa[nt][0] = f2bf2(p00, p01);
            pa[nt][1] = f2bf2(p10, p11);
        }
        ps0 += __shfl_xor_sync(0xffffffffu, ps0, 1);
        ps0 += __shfl_xor_sync(0xffffffffu, ps0, 2);
        ps1 += __shfl_xor_sync(0xffffffffu, ps1, 1);
        ps1 += __shfl_xor_sync(0xffffffffu, ps1, 2);
        l0 = l0 * f0 + ps0;
        l1 = l1 * f1 + ps1;
#pragma unroll
        for (int nt = 0; nt < 4; nt++) {
            oacc[nt][0] *= f0; oacc[nt][1] *= f0;
            oacc[nt][2] *= f1; oacc[nt][3] *= f1;
        }

        // ---- O += P @ V : P straight from registers (S-frag == A-frag) ----
#pragma unroll
        for (int ks = 0; ks < 8; ks++) {
            uint32_t afr[4] = { pa[2 * ks][0], pa[2 * ks][1],
                                pa[2 * ks + 1][0], pa[2 * ks + 1][1] };
#pragma unroll
            for (int nt = 0; nt < 4; nt++) {
                uint32_t bfr[2];
                bfr[0] = sVt[buf][(nt * 8 + g) * VS + ks * 8 + tg];
                bfr[1] = sVt[buf][(nt * 8 + g) * VS + ks * 8 + tg + 4];
                mma_bf16(oacc[nt], afr, bfr);
            }
        }

        if (kt < 15) {
#pragma unroll
            for (int i = 0; i < 8; i++) {
                uint32_t o = __shfl_xor_sync(0xffffffffu, vv[i], 2);
                if (keyeven) sVt[nbuf][(half * 16 + 2 * i    ) * VS + colp] = __byte_perm(vv[i], o, 0x5410);
                else         sVt[nbuf][(half * 16 + 2 * i + 1) * VS + colp] = __byte_perm(vv[i], o, 0x3276);
            }
            CP_WAIT(0);
        }
        __syncthreads();
    }

    // ---- epilogue: write bf16 attention output ----
    float inv0 = 1.0f / l0, inv1 = 1.0f / l1;
    int q0 = qt * 128 + w * 16 + g;
    uint32_t* op0 = (uint32_t*)((uint16_t*)outb + (size_t)(b * N_ + q0) * C_ + h * DH_);
    uint32_t* op1 = (uint32_t*)((uint16_t*)outb + (size_t)(b * N_ + q0 + 8) * C_ + h * DH_);
#pragma unroll
    for (int nt = 0; nt < 4; nt++) {
        op0[nt * 4 + tg] = f2bf2(oacc[nt][0] * inv0, oacc[nt][1] * inv0);
        op1[nt * 4 + tg] = f2bf2(oacc[nt][2] * inv1, oacc[nt][3] * inv1);
    }
}

// ===================== fused residual add + layernorm (fp32 + bf16 out) ==========
__global__ __launch_bounds__(256) void add_ln_kernel(
    const float* __restrict__ x, const float* __restrict__ y,
    const float* __restrict__ g, const float* __restrict__ be,
    float* __restrict__ out, __nv_bfloat16* __restrict__ outb)
{
    int row = blockIdx.x;
    int c = threadIdx.x;
    float v = x[(size_t)row * C_ + c] + y[(size_t)row * C_ + c];

    __shared__ float red[8];
    float s = v;
#pragma unroll
    for (int o = 16; o > 0; o >>= 1) s += __shfl_down_sync(0xffffffffu, s, o);
    if ((c & 31) == 0) red[c >> 5] = s;
    __syncthreads();
    float mu = 0.f;
#pragma unroll
    for (int i = 0; i < 8; i++) mu += red[i];
    mu *= (1.0f / C_);
    __syncthreads();
    float dv = v - mu;
    float s2 = dv * dv;
#pragma unroll
    for (int o = 16; o > 0; o >>= 1) s2 += __shfl_down_sync(0xffffffffu, s2, o);
    if ((c & 31) == 0) red[c >> 5] = s2;
    __syncthreads();
    float var = 0.f;
#pragma unroll
    for (int i = 0; i < 8; i++) var += red[i];
    var *= (1.0f / C_);

    float r = dv * rsqrtf(var + 1e-6f) * g[c] + be[c];
    out[(size_t)row * C_ + c] = r;
    outb[(size_t)row * C_ + c] = __float2bfloat16(r);
}

// ===================== launch =====================
extern "C" void kernel_launch(void* const* d_in, const int* in_sizes, int n_in,
                              void* d_out, int out_size)
{
    const float* x_in   = (const float*)d_in[0];
    const float* qkv_w  = (const float*)d_in[1];
    const float* proj_w = (const float*)d_in[2];
    const float* proj_b = (const float*)d_in[3];
    const float* w1     = (const float*)d_in[4];
    const float* b1     = (const float*)d_in[5];
    const float* w2     = (const float*)d_in[6];
    const float* b2     = (const float*)d_in[7];
    const float* g1     = (const float*)d_in[8];
    const float* be1    = (const float*)d_in[9];
    const float* g2     = (const float*)d_in[10];
    const float* be2    = (const float*)d_in[11];
    float* out = (float*)d_out;

    float *px, *ptmp;
    __nv_bfloat16 *pxb, *pqkvb, *pattnb, *phb;
    __nv_bfloat16 *pqkvT, *pprojT, *pw1T, *pw2T;
    cudaGetSymbolAddress((void**)&px,    g_x);
    cudaGetSymbolAddress((void**)&ptmp,  g_tmp);
    cudaGetSymbolAddress((void**)&pxb,   g_xb);
    cudaGetSymbolAddress((void**)&pqkvb, g_qkvb);
    cudaGetSymbolAddress((void**)&pattnb,g_attnb);
    cudaGetSymbolAddress((void**)&phb,   g_hb);
    cudaGetSymbolAddress((void**)&pqkvT, g_qkvT);
    cudaGetSymbolAddress((void**)&pprojT,g_projT);
    cudaGetSymbolAddress((void**)&pw1T,  g_w1T);
    cudaGetSymbolAddress((void**)&pw2T,  g_w2T);

    static bool attr_done = false;
    if (!attr_done) {
        cudaFuncSetAttribute(gemm_mma_kernel,
                             cudaFuncAttributeMaxDynamicSharedMemorySize, 55296);
        attr_done = true;
    }

    transpose_kernel<<<dim3(QKV_N_ / 32, C_ / 32, L_), dim3(32, 8)>>>(qkv_w, pqkvT, C_, QKV_N_);
    transpose_kernel<<<dim3(C_ / 32, C_ / 32, L_),     dim3(32, 8)>>>(proj_w, pprojT, C_, C_);
    transpose_kernel<<<dim3(C_ / 32, C_ / 32, L_),     dim3(32, 8)>>>(w1, pw1T, C_, C_);
    transpose_kernel<<<dim3(C_ / 32, C_ / 32, L_),     dim3(32, 8)>>>(w2, pw2T, C_, C_);

    addpos_kernel<<<N_, C_>>>(x_in, px, pxb);

    for (int l = 0; l < L_; l++) {
        // qkv = x @ qkv_w[l]  -> bf16
        gemm_mma_kernel<<<dim3(QKV_N_ / 64, ROWS_ / 128), 256, 55296>>>(
            pxb, pqkvT + (size_t)l * QKV_N_ * C_, nullptr, pqkvb, QKV_N_, 0);
        // attention -> bf16
        attn_mma_kernel<<<dim3(N_ / 128, H_, B_), 256>>>(pqkvb, pattnb);
        // proj -> fp32
        gemm_mma_kernel<<<dim3(C_ / 64, ROWS_ / 128), 256, 55296>>>(
            pattnb, pprojT + (size_t)l * C_ * C_, proj_b + (size_t)l * C_, ptmp, C_, 1);
        // x = LN(x + proj_out)
        add_ln_kernel<<<ROWS_, C_>>>(px, ptmp, g1 + (size_t)l * C_, be1 + (size_t)l * C_, px, pxb);
        // h = gelu(x @ w1 + b1) -> bf16
        gemm_mma_kernel<<<dim3(C_ / 64, ROWS_ / 128), 256, 55296>>>(
            pxb, pw1T + (size_t)l * C_ * C_, b1 + (size_t)l * C_, phb, C_, 2);
        // mlp = h @ w2 + b2 -> fp32
        gemm_mma_kernel<<<dim3(C_ / 64, ROWS_ / 128), 256, 55296>>>(
            phb, pw2T + (size_t)l * C_ * C_, b2 + (size_t)l * C_, ptmp, C_, 1);
        // x = LN(x + mlp); final layer -> d_out
        float* dst = (l == L_ - 1) ? out : px;
        add_ln_kernel<<<ROWS_, C_>>>(px, ptmp, g2 + (size_t)l * C_, be2 + (size_t)l * C_, dst, pxb);
    }
}

// round 6
// speedup vs baseline: 1.5149x; 1.5149x over previous
#include <cuda_runtime.h>
#include <cuda_bf16.h>
#include <math.h>
#include <stdint.h>

#define B_ 2
#define N_ 2048
#define C_ 256
#define L_ 4
#define H_ 8
#define DH_ 32
#define ROWS_ (B_ * N_)          // 4096
#define QKV_N_ (3 * C_)          // 768
#define QSC_ (0.17677669529663687f * 1.4426950408889634f)   // 1/sqrt(32) * log2e

// ===================== scratch =====================
__device__ float          g_x   [ROWS_ * C_];
__device__ float          g_tmp [ROWS_ * C_];
__device__ __nv_bfloat16  g_xb  [ROWS_ * C_];
__device__ __nv_bfloat16  g_qkvb[ROWS_ * QKV_N_];
__device__ __nv_bfloat16  g_attnb[ROWS_ * C_];
__device__ __nv_bfloat16  g_hb  [ROWS_ * C_];
__device__ __nv_bfloat16  g_qkvT [L_ * QKV_N_ * C_];
__device__ __nv_bfloat16  g_projT[L_ * C_ * C_];
__device__ __nv_bfloat16  g_w1T  [L_ * C_ * C_];
__device__ __nv_bfloat16  g_w2T  [L_ * C_ * C_];

// ===================== helpers =====================
__device__ __forceinline__ float ex2(float x) {
    float y;
    asm("ex2.approx.ftz.f32 %0, %1;" : "=f"(y) : "f"(x));
    return y;
}

__device__ __forceinline__ uint32_t f2bf2(float lo, float hi) {
    uint32_t r;
    asm("cvt.rn.bf16x2.f32 %0, %1, %2;" : "=r"(r) : "f"(hi), "f"(lo));
    return r;
}

__device__ __forceinline__ void mma_bf16(float* d, const uint32_t* a, const uint32_t* b) {
    asm volatile(
        "mma.sync.aligned.m16n8k16.row.col.f32.bf16.bf16.f32 "
        "{%0,%1,%2,%3}, {%4,%5,%6,%7}, {%8,%9}, {%0,%1,%2,%3};"
        : "+f"(d[0]), "+f"(d[1]), "+f"(d[2]), "+f"(d[3])
        : "r"(a[0]), "r"(a[1]), "r"(a[2]), "r"(a[3]), "r"(b[0]), "r"(b[1]));
}

__device__ __forceinline__ uint32_t su32(const void* p) {
    uint32_t a;
    asm("{ .reg .u64 t; cvta.to.shared.u64 t, %1; cvt.u32.u64 %0, t; }" : "=r"(a) : "l"(p));
    return a;
}

__device__ __forceinline__ void cp16(uint32_t dst, const void* src) {
    asm volatile("cp.async.ca.shared.global [%0], [%1], 16;" :: "r"(dst), "l"(src));
}
#define CP_COMMIT() asm volatile("cp.async.commit_group;" ::: "memory")
#define CP_WAIT(Ng) asm volatile("cp.async.wait_group %0;" :: "n"(Ng) : "memory")

// ===================== weight transpose + bf16 convert =====================
__global__ __launch_bounds__(256) void transpose_kernel(
    const float* __restrict__ in, __nv_bfloat16* __restrict__ out, int K, int Nn)
{
    __shared__ float t[32][33];
    int z = blockIdx.z;
    const float* inl = in + (size_t)z * K * Nn;
    __nv_bfloat16* outl = out + (size_t)z * Nn * K;
    int tx = threadIdx.x, ty = threadIdx.y;
    int x = blockIdx.x * 32 + tx;
    int y = blockIdx.y * 32 + ty;
#pragma unroll
    for (int j = 0; j < 4; j++)
        t[ty + 8 * j][tx] = inl[(size_t)(y + 8 * j) * Nn + x];
    __syncthreads();
    int x2 = blockIdx.y * 32 + tx;
    int y2 = blockIdx.x * 32 + ty;
#pragma unroll
    for (int j = 0; j < 4; j++)
        outl[(size_t)(y2 + 8 * j) * K + x2] = __float2bfloat16(t[tx][ty + 8 * j]);
}

// ===================== positional embedding add =====================
__global__ void addpos_kernel(const float* __restrict__ x,
                              float* __restrict__ out, __nv_bfloat16* __restrict__ outb)
{
    int n = blockIdx.x;
    int c = threadIdx.x;
    int j = c & ~1;
    float div = __expf((float)j * (-9.210340371976184f / 256.0f));
    float ang = (float)n * div;
    float pe = (c & 1) ? cosf(ang) : sinf(ang);
    size_t i0 = (size_t)n * C_ + c;
    size_t i1 = (size_t)(N_ + n) * C_ + c;
    float v0 = x[i0] + pe, v1 = x[i1] + pe;
    out[i0] = v0; out[i1] = v1;
    outb[i0] = __float2bfloat16(v0);
    outb[i1] = __float2bfloat16(v1);
}

// ===================== bf16 mma GEMM: 64x64 tile, 4 warps ====================
// grid (Nn/64, 64), 128 thr; warp tile 32x32; K=256 in 4 chunks of 64, cp.async DB.
// mode: 0 = bf16 out; 1 = fp32 out + bias; 2 = bf16 out + bias + gelu
#define AS 36   // smem row stride in u32 (32 data + 4 pad)

__global__ __launch_bounds__(128) void gemm_mma_kernel(
    const __nv_bfloat16* __restrict__ A, const __nv_bfloat16* __restrict__ BT,
    const float* __restrict__ bias, void* __restrict__ Cc, int Nn, int mode)
{
    extern __shared__ __align__(16) uint32_t gsm[];
    uint32_t* sAb[2] = {gsm,                gsm + 64 * AS};
    uint32_t* sBb[2] = {gsm + 2 * 64 * AS,  gsm + 3 * 64 * AS};

    const int tid = threadIdx.x, w = tid >> 5, lane = tid & 31;
    const int g = lane >> 2, tg = lane & 3;
    const int wm = (w & 1) * 32, wn = (w >> 1) * 32;
    const int brow = blockIdx.y * 64, bcol = blockIdx.x * 64;

    float acc[2][4][4];
#pragma unroll
    for (int mt = 0; mt < 2; mt++)
#pragma unroll
        for (int nt = 0; nt < 4; nt++)
#pragma unroll
            for (int i = 0; i < 4; i++) acc[mt][nt][i] = 0.f;

    const int srow = tid >> 1, half = tid & 1;      // 64 rows, 64B per thread
    const char* asrc = (const char*)A  + (size_t)(brow + srow) * 512 + half * 64;
    const char* bsrc = (const char*)BT + (size_t)(bcol + srow) * 512 + half * 64;
    const uint32_t adst[2] = { su32(&sAb[0][srow * AS + half * 16]),
                               su32(&sAb[1][srow * AS + half * 16]) };
    const uint32_t bdst[2] = { su32(&sBb[0][srow * AS + half * 16]),
                               su32(&sBb[1][srow * AS + half * 16]) };

#pragma unroll
    for (int j = 0; j < 4; j++) { cp16(adst[0] + j * 16, asrc + j * 16);
                                  cp16(bdst[0] + j * 16, bsrc + j * 16); }
    CP_COMMIT();

#pragma unroll
    for (int it = 0; it < 4; it++) {
        const int buf = it & 1;
        if (it < 3) {
            const int nb = buf ^ 1;
#pragma unroll
            for (int j = 0; j < 4; j++) {
                cp16(adst[nb] + j * 16, asrc + (it + 1) * 128 + j * 16);
                cp16(bdst[nb] + j * 16, bsrc + (it + 1) * 128 + j * 16);
            }
            CP_COMMIT();
            CP_WAIT(1);
        } else {
            CP_WAIT(0);
        }
        __syncthreads();
#pragma unroll
        for (int ks = 0; ks < 4; ks++) {
            uint32_t afr[2][4];
#pragma unroll
            for (int mt = 0; mt < 2; mt++) {
                int r = wm + mt * 16 + g;
                afr[mt][0] = sAb[buf][(r    ) * AS + ks * 8 + tg];
                afr[mt][1] = sAb[buf][(r + 8) * AS + ks * 8 + tg];
                afr[mt][2] = sAb[buf][(r    ) * AS + ks * 8 + tg + 4];
                afr[mt][3] = sAb[buf][(r + 8) * AS + ks * 8 + tg + 4];
            }
#pragma unroll
            for (int nt = 0; nt < 4; nt++) {
                int n = wn + nt * 8 + g;
                uint32_t bfr[2];
                bfr[0] = sBb[buf][n * AS + ks * 8 + tg];
                bfr[1] = sBb[buf][n * AS + ks * 8 + tg + 4];
#pragma unroll
                for (int mt = 0; mt < 2; mt++) mma_bf16(acc[mt][nt], afr[mt], bfr);
            }
        }
        __syncthreads();
    }

#pragma unroll
    for (int mt = 0; mt < 2; mt++) {
        int r0 = brow + wm + mt * 16 + g;
#pragma unroll
        for (int nt = 0; nt < 4; nt++) {
            int cc = bcol + wn + nt * 8 + 2 * tg;
            float bi0 = 0.f, bi1 = 0.f;
            if (mode >= 1) { bi0 = bias[cc]; bi1 = bias[cc + 1]; }
            float v0 = acc[mt][nt][0] + bi0;
            float v1 = acc[mt][nt][1] + bi1;
            float v2 = acc[mt][nt][2] + bi0;
            float v3 = acc[mt][nt][3] + bi1;
            if (mode == 2) {
                v0 = 0.5f * v0 * (1.0f + erff(v0 * 0.70710678118654752f));
                v1 = 0.5f * v1 * (1.0f + erff(v1 * 0.70710678118654752f));
                v2 = 0.5f * v2 * (1.0f + erff(v2 * 0.70710678118654752f));
                v3 = 0.5f * v3 * (1.0f + erff(v3 * 0.70710678118654752f));
            }
            if (mode == 1) {
                float* dst = (float*)Cc;
                *(float2*)(dst + (size_t)r0 * Nn + cc)       = make_float2(v0, v1);
                *(float2*)(dst + (size_t)(r0 + 8) * Nn + cc) = make_float2(v2, v3);
            } else {
                uint32_t* dst = (uint32_t*)Cc;
                dst[((size_t)r0 * Nn + cc) >> 1]       = f2bf2(v0, v1);
                dst[((size_t)(r0 + 8) * Nn + cc) >> 1] = f2bf2(v2, v3);
            }
        }
    }
}

// ===================== bf16 mma flash attention (P in regs, 64-key halves) ========
#define QS 20
#define VS 68
#define KROWB ((size_t)128 * QKV_N_ * 2)

__global__ __launch_bounds__(256, 2) void attn_mma_kernel(
    const __nv_bfloat16* __restrict__ qkvb, __nv_bfloat16* __restrict__ outb)
{
    __shared__ __align__(16) uint32_t sQ[128 * QS];
    __shared__ __align__(16) uint32_t sK[2][128 * QS];
    __shared__ __align__(16) uint32_t sVt[2][32 * VS];

    const int tid = threadIdx.x, w = tid >> 5, lane = tid & 31;
    const int g = lane >> 2, tg = lane & 3;
    const int qt = blockIdx.x, h = blockIdx.y, b = blockIdx.z;

    const int srow = tid >> 1, half = tid & 1;
    const int colp = tid >> 2;
    const bool keyeven = (tid & 2) == 0;

    const char* qsrc = (const char*)qkvb +
        ((size_t)(b * N_ + qt * 128 + srow) * QKV_N_ + h * DH_) * 2 + half * 32;
    const char* ksrc = (const char*)qkvb +
        ((size_t)(b * N_ + srow) * QKV_N_ + C_ + h * DH_) * 2 + half * 32;
    const char* vsrc = (const char*)qkvb +
        ((size_t)(b * N_ + srow) * QKV_N_ + 2 * C_ + h * DH_) * 2 + half * 32;

    const uint32_t qdst = su32(&sQ[srow * QS + half * 8]);
    const uint32_t kdst[2] = { su32(&sK[0][srow * QS + half * 8]),
                               su32(&sK[1][srow * QS + half * 8]) };

    cp16(qdst, qsrc);           cp16(qdst + 16, qsrc + 16);
    cp16(kdst[0], ksrc);        cp16(kdst[0] + 16, ksrc + 16);
    CP_COMMIT();
    {
        const uint4* vp = (const uint4*)vsrc;
        uint4 v0 = vp[0], v1 = vp[1];
        uint32_t vv[8] = {v0.x, v0.y, v0.z, v0.w, v1.x, v1.y, v1.z, v1.w};
#pragma unroll
        for (int i = 0; i < 8; i++) {
            uint32_t o = __shfl_xor_sync(0xffffffffu, vv[i], 2);
            if (keyeven) sVt[0][(half * 16 + 2 * i    ) * VS + colp] = __byte_perm(vv[i], o, 0x5410);
            else         sVt[0][(half * 16 + 2 * i + 1) * VS + colp] = __byte_perm(vv[i], o, 0x3276);
        }
    }
    CP_WAIT(0);
    __syncthreads();

    float oacc[4][4];
#pragma unroll
    for (int nt = 0; nt < 4; nt++)
#pragma unroll
        for (int i = 0; i < 4; i++) oacc[nt][i] = 0.f;
    float m0 = -1e30f, m1 = -1e30f, l0 = 0.f, l1 = 0.f;

    // Q fragments are loop-invariant: hoist
    uint32_t qfr[2][4];
#pragma unroll
    for (int ks = 0; ks < 2; ks++) {
        qfr[ks][0] = sQ[(w * 16 + g    ) * QS + ks * 8 + tg];
        qfr[ks][1] = sQ[(w * 16 + g + 8) * QS + ks * 8 + tg];
        qfr[ks][2] = sQ[(w * 16 + g    ) * QS + ks * 8 + tg + 4];
        qfr[ks][3] = sQ[(w * 16 + g + 8) * QS + ks * 8 + tg + 4];
    }

    for (int kt = 0; kt < N_ / 128; kt++) {
        const int buf = kt & 1, nbuf = buf ^ 1;
        uint32_t vv[8];
        if (kt < 15) {
            const char* ks2 = ksrc + (size_t)(kt + 1) * KROWB;
            cp16(kdst[nbuf], ks2); cp16(kdst[nbuf] + 16, ks2 + 16);
            CP_COMMIT();
            const uint4* vp = (const uint4*)(vsrc + (size_t)(kt + 1) * KROWB);
            uint4 v0 = vp[0], v1 = vp[1];
            vv[0] = v0.x; vv[1] = v0.y; vv[2] = v0.z; vv[3] = v0.w;
            vv[4] = v1.x; vv[5] = v1.y; vv[6] = v1.z; vv[7] = v1.w;
        }

        // two 64-key halves, each an independent online-softmax step
#pragma unroll
        for (int h2 = 0; h2 < 2; h2++) {
            float sacc[8][4];
#pragma unroll
            for (int nt = 0; nt < 8; nt++)
#pragma unroll
                for (int i = 0; i < 4; i++) sacc[nt][i] = 0.f;
#pragma unroll
            for (int ks = 0; ks < 2; ks++) {
#pragma unroll
                for (int nt = 0; nt < 8; nt++) {
                    uint32_t bfr[2];
                    int kr = h2 * 64 + nt * 8 + g;
                    bfr[0] = sK[buf][kr * QS + ks * 8 + tg];
                    bfr[1] = sK[buf][kr * QS + ks * 8 + tg + 4];
                    mma_bf16(sacc[nt], qfr[ks], bfr);
                }
            }

            float nm0 = m0, nm1 = m1;
#pragma unroll
            for (int nt = 0; nt < 8; nt++) {
                nm0 = fmaxf(nm0, fmaxf(sacc[nt][0], sacc[nt][1]));
                nm1 = fmaxf(nm1, fmaxf(sacc[nt][2], sacc[nt][3]));
            }
            nm0 = fmaxf(nm0, __shfl_xor_sync(0xffffffffu, nm0, 1));
            nm0 = fmaxf(nm0, __shfl_xor_sync(0xffffffffu, nm0, 2));
            nm1 = fmaxf(nm1, __shfl_xor_sync(0xffffffffu, nm1, 1));
            nm1 = fmaxf(nm1, __shfl_xor_sync(0xffffffffu, nm1, 2));
            float f0 = ex2((m0 - nm0) * QSC_), f1 = ex2((m1 - nm1) * QSC_);
            m0 = nm0; m1 = nm1;

            uint32_t pa[8][2];
            float ps0 = 0.f, ps1 = 0.f;
#pragma unroll
            for (int nt = 0; nt < 8; nt++) {
                float p00 = ex2((sacc[nt][0] - m0) * QSC_);
                float p01 = ex2((sacc[nt][1] - m0) * QSC_);
                float p10 = ex2((sacc[nt][2] - m1) * QSC_);
                float p11 = ex2((sacc[nt][3] - m1) * QSC_);
                ps0 += p00 + p01;
                ps1 += p10 + p11;
                pa[nt][0] = f2bf2(p00, p01);
                pa[nt][1] = f2bf2(p10, p11);
            }
            ps0 += __shfl_xor_sync(0xffffffffu, ps0, 1);
            ps0 += __shfl_xor_sync(0xffffffffu, ps0, 2);
            ps1 += __shfl_xor_sync(0xffffffffu, ps1, 1);
            ps1 += __shfl_xor_sync(0xffffffffu, ps1, 2);
            l0 = l0 * f0 + ps0;
            l1 = l1 * f1 + ps1;
#pragma unroll
            for (int nt = 0; nt < 4; nt++) {
                oacc[nt][0] *= f0; oacc[nt][1] *= f0;
                oacc[nt][2] *= f1; oacc[nt][3] *= f1;
            }

            // O += P @ V over this half's 64 keys (4 k16 steps)
#pragma unroll
            for (int j = 0; j < 4; j++) {
                uint32_t afr[4] = { pa[2 * j][0], pa[2 * j][1],
                                    pa[2 * j + 1][0], pa[2 * j + 1][1] };
                int ksg = h2 * 4 + j;
#pragma unroll
                for (int nt = 0; nt < 4; nt++) {
                    uint32_t bfr[2];
                    bfr[0] = sVt[buf][(nt * 8 + g) * VS + ksg * 8 + tg];
                    bfr[1] = sVt[buf][(nt * 8 + g) * VS + ksg * 8 + tg + 4];
                    mma_bf16(oacc[nt], afr, bfr);
                }
            }
        }

        if (kt < 15) {
#pragma unroll
            for (int i = 0; i < 8; i++) {
                uint32_t o = __shfl_xor_sync(0xffffffffu, vv[i], 2);
                if (keyeven) sVt[nbuf][(half * 16 + 2 * i    ) * VS + colp] = __byte_perm(vv[i], o, 0x5410);
                else         sVt[nbuf][(half * 16 + 2 * i + 1) * VS + colp] = __byte_perm(vv[i], o, 0x3276);
            }
            CP_WAIT(0);
        }
        __syncthreads();
    }

    float inv0 = 1.0f / l0, inv1 = 1.0f / l1;
    int q0 = qt * 128 + w * 16 + g;
    uint32_t* op0 = (uint32_t*)((uint16_t*)outb + (size_t)(b * N_ + q0) * C_ + h * DH_);
    uint32_t* op1 = (uint32_t*)((uint16_t*)outb + (size_t)(b * N_ + q0 + 8) * C_ + h * DH_);
#pragma unroll
    for (int nt = 0; nt < 4; nt++) {
        op0[nt * 4 + tg] = f2bf2(oacc[nt][0] * inv0, oacc[nt][1] * inv0);
        op1[nt * 4 + tg] = f2bf2(oacc[nt][2] * inv1, oacc[nt][3] * inv1);
    }
}

// ===================== fused residual add + layernorm =====================
__global__ __launch_bounds__(256) void add_ln_kernel(
    const float* __restrict__ x, const float* __restrict__ y,
    const float* __restrict__ g, const float* __restrict__ be,
    float* __restrict__ out, __nv_bfloat16* __restrict__ outb)
{
    int row = blockIdx.x;
    int c = threadIdx.x;
    float v = x[(size_t)row * C_ + c] + y[(size_t)row * C_ + c];

    __shared__ float red[8];
    float s = v;
#pragma unroll
    for (int o = 16; o > 0; o >>= 1) s += __shfl_down_sync(0xffffffffu, s, o);
    if ((c & 31) == 0) red[c >> 5] = s;
    __syncthreads();
    float mu = 0.f;
#pragma unroll
    for (int i = 0; i < 8; i++) mu += red[i];
    mu *= (1.0f / C_);
    __syncthreads();
    float dv = v - mu;
    float s2 = dv * dv;
#pragma unroll
    for (int o = 16; o > 0; o >>= 1) s2 += __shfl_down_sync(0xffffffffu, s2, o);
    if ((c & 31) == 0) red[c >> 5] = s2;
    __syncthreads();
    float var = 0.f;
#pragma unroll
    for (int i = 0; i < 8; i++) var += red[i];
    var *= (1.0f / C_);

    float r = dv * rsqrtf(var + 1e-6f) * g[c] + be[c];
    out[(size_t)row * C_ + c] = r;
    outb[(size_t)row * C_ + c] = __float2bfloat16(r);
}

// ===================== launch =====================
extern "C" void kernel_launch(void* const* d_in, const int* in_sizes, int n_in,
                              void* d_out, int out_size)
{
    const float* x_in   = (const float*)d_in[0];
    const float* qkv_w  = (const float*)d_in[1];
    const float* proj_w = (const float*)d_in[2];
    const float* proj_b = (const float*)d_in[3];
    const float* w1     = (const float*)d_in[4];
    const float* b1     = (const float*)d_in[5];
    const float* w2     = (const float*)d_in[6];
    const float* b2     = (const float*)d_in[7];
    const float* g1     = (const float*)d_in[8];
    const float* be1    = (const float*)d_in[9];
    const float* g2     = (const float*)d_in[10];
    const float* be2    = (const float*)d_in[11];
    float* out = (float*)d_out;

    float *px, *ptmp;
    __nv_bfloat16 *pxb, *pqkvb, *pattnb, *phb;
    __nv_bfloat16 *pqkvT, *pprojT, *pw1T, *pw2T;
    cudaGetSymbolAddress((void**)&px,    g_x);
    cudaGetSymbolAddress((void**)&ptmp,  g_tmp);
    cudaGetSymbolAddress((void**)&pxb,   g_xb);
    cudaGetSymbolAddress((void**)&pqkvb, g_qkvb);
    cudaGetSymbolAddress((void**)&pattnb,g_attnb);
    cudaGetSymbolAddress((void**)&phb,   g_hb);
    cudaGetSymbolAddress((void**)&pqkvT, g_qkvT);
    cudaGetSymbolAddress((void**)&pprojT,g_projT);
    cudaGetSymbolAddress((void**)&pw1T,  g_w1T);
    cudaGetSymbolAddress((void**)&pw2T,  g_w2T);

    const int GEMM_SMEM = 4 * 64 * AS * 4;   // 36864 B

    // launch order chosen so ncu (-s 5 -c 1) captures attention layer 0 (launch #5)
    transpose_kernel<<<dim3(QKV_N_ / 32, C_ / 32, L_), dim3(32, 8)>>>(qkv_w, pqkvT, C_, QKV_N_);  // 0
    addpos_kernel<<<N_, C_>>>(x_in, px, pxb);                                                      // 1
    gemm_mma_kernel<<<dim3(QKV_N_ / 64, ROWS_ / 64), 128, GEMM_SMEM>>>(                            // 2
        pxb, pqkvT, nullptr, pqkvb, QKV_N_, 0);
    transpose_kernel<<<dim3(C_ / 32, C_ / 32, L_), dim3(32, 8)>>>(proj_w, pprojT, C_, C_);         // 3
    transpose_kernel<<<dim3(C_ / 32, C_ / 32, L_), dim3(32, 8)>>>(w1, pw1T, C_, C_);               // 4
    attn_mma_kernel<<<dim3(N_ / 128, H_, B_), 256>>>(pqkvb, pattnb);                               // 5 <- profiled
    transpose_kernel<<<dim3(C_ / 32, C_ / 32, L_), dim3(32, 8)>>>(w2, pw2T, C_, C_);               // 6

    for (int l = 0; l < L_; l++) {
        if (l > 0) {
            gemm_mma_kernel<<<dim3(QKV_N_ / 64, ROWS_ / 64), 128, GEMM_SMEM>>>(
                pxb, pqkvT + (size_t)l * QKV_N_ * C_, nullptr, pqkvb, QKV_N_, 0);
            attn_mma_kernel<<<dim3(N_ / 128, H_, B_), 256>>>(pqkvb, pattnb);
        }
        gemm_mma_kernel<<<dim3(C_ / 64, ROWS_ / 64), 128, GEMM_SMEM>>>(
            pattnb, pprojT + (size_t)l * C_ * C_, proj_b + (size_t)l * C_, ptmp, C_, 1);
        add_ln_kernel<<<ROWS_, C_>>>(px, ptmp, g1 + (size_t)l * C_, be1 + (size_t)l * C_, px, pxb);
        gemm_mma_kernel<<<dim3(C_ / 64, ROWS_ / 64), 128, GEMM_SMEM>>>(
            pxb, pw1T + (size_t)l * C_ * C_, b1 + (size_t)l * C_, phb, C_, 2);
        gemm_mma_kernel<<<dim3(C_ / 64, ROWS_ / 64), 128, GEMM_SMEM>>>(
            phb, pw2T + (size_t)l * C_ * C_, b2 + (size_t)l * C_, ptmp, C_, 1);
        float* dst = (l == L_ - 1) ? out : px;
        add_ln_kernel<<<ROWS_, C_>>>(px, ptmp, g2 + (size_t)l * C_, be2 + (size_t)l * C_, dst, pxb);
    }
}